// round 4
// baseline (speedup 1.0000x reference)
#include <cuda_runtime.h>

typedef unsigned long long u64;

#define NBATCH 512
#define CIN 128
#define LIN 1024
#define LOUT 1020
#define TSEQ 1020

// conv output in [b][ch][pos] layout == seq [b][t][128] flattened (pure re-view)
__device__ float g_conv[NBATCH * CIN * LOUT];
__device__ float g_xg[NBATCH * TSEQ * 128];

__device__ __forceinline__ u64 fma2(u64 a, u64 b, u64 c){
    u64 d; asm("fma.rn.f32x2 %0, %1, %2, %3;" : "=l"(d) : "l"(a), "l"(b), "l"(c)); return d;
}
__device__ __forceinline__ u64 pack2(float lo, float hi){
    u64 d; asm("mov.b64 %0, {%1, %2};" : "=l"(d) : "f"(lo), "f"(hi)); return d;
}
__device__ __forceinline__ float lo32(u64 v){ return __uint_as_float((unsigned)(v & 0xffffffffu)); }
__device__ __forceinline__ float hi32(u64 v){ return __uint_as_float((unsigned)(v >> 32)); }

// ---------------------------------------------------------------------------
// Kernel 1: conv1d 128->128, k=5, VALID. Implicit GEMM, f32x2-packed FMAs.
// Block: one batch b, one 128-wide p tile, all 128 output channels.
// Thread: 8 oc (as 4 f32x2 pairs) x 8 p micro-tile.
// ---------------------------------------------------------------------------
__global__ __launch_bounds__(256) void conv_kernel(
    const float* __restrict__ x, const float* __restrict__ w, const float* __restrict__ bias)
{
    const int b   = blockIdx.y;
    const int p0  = blockIdx.x * 128;
    const int tid = threadIdx.x;
    const int tx  = tid & 15;      // p micro index
    const int ty  = tid >> 4;      // oc micro index
    const int oc0 = ty * 8;
    const int pp0 = tx * 8;

    __shared__ __align__(16) float xs[8][136];   // x chunk: 8 ic x 132 pos (padded)
    __shared__ __align__(16) float ws[40][128];  // w chunk: k=(ic_l*5+j) x 128 oc

    u64 acc[4][8];
    #pragma unroll
    for (int m = 0; m < 4; m++)
        #pragma unroll
        for (int n = 0; n < 8; n++) acc[m][n] = 0ULL;

    const float* xb = x + (long)b * (CIN * LIN);

    for (int ic0 = 0; ic0 < CIN; ic0 += 8) {
        for (int idx = tid; idx < 8 * 132; idx += 256) {
            int r = idx / 132, c = idx - r * 132;
            int gp = p0 + c;
            xs[r][c] = (gp < LIN) ? xb[(ic0 + r) * LIN + gp] : 0.f;
        }
        for (int idx = tid; idx < 40 * 128; idx += 256) {
            int k = idx >> 7, oc = idx & 127;
            int icl = k / 5, j = k - icl * 5;
            ws[k][oc] = w[(oc * CIN + (ic0 + icl)) * 5 + j];
        }
        __syncthreads();
        for (int icl = 0; icl < 8; icl++) {
            // 12-float sliding window for this ic row, pre-packed as (v,v) pairs
            const float4* wp = reinterpret_cast<const float4*>(&xs[icl][pp0]);
            float4 v0 = wp[0], v1 = wp[1], v2 = wp[2];
            u64 pw[12];
            pw[0]=pack2(v0.x,v0.x); pw[1]=pack2(v0.y,v0.y); pw[2]=pack2(v0.z,v0.z); pw[3]=pack2(v0.w,v0.w);
            pw[4]=pack2(v1.x,v1.x); pw[5]=pack2(v1.y,v1.y); pw[6]=pack2(v1.z,v1.z); pw[7]=pack2(v1.w,v1.w);
            pw[8]=pack2(v2.x,v2.x); pw[9]=pack2(v2.y,v2.y); pw[10]=pack2(v2.z,v2.z); pw[11]=pack2(v2.w,v2.w);
            #pragma unroll
            for (int j = 0; j < 5; j++) {
                const u64* ap = reinterpret_cast<const u64*>(&ws[icl * 5 + j][oc0]);
                u64 a0 = ap[0], a1 = ap[1], a2 = ap[2], a3 = ap[3];
                #pragma unroll
                for (int n = 0; n < 8; n++) {
                    u64 bb = pw[j + n];
                    acc[0][n] = fma2(a0, bb, acc[0][n]);
                    acc[1][n] = fma2(a1, bb, acc[1][n]);
                    acc[2][n] = fma2(a2, bb, acc[2][n]);
                    acc[3][n] = fma2(a3, bb, acc[3][n]);
                }
            }
        }
        __syncthreads();
    }

    float* ob = g_conv + (long)b * (CIN * LOUT);
    #pragma unroll
    for (int m = 0; m < 4; m++) {
        int oce = oc0 + 2 * m;
        float be = bias[oce], bo = bias[oce + 1];
        #pragma unroll
        for (int n = 0; n < 8; n++) {
            int p = p0 + pp0 + n;
            if (p < LOUT) {
                ob[oce * LOUT + p]       = lo32(acc[m][n]) + be;
                ob[(oce + 1) * LOUT + p] = hi32(acc[m][n]) + bo;
            }
        }
    }
}

// ---------------------------------------------------------------------------
// Kernel 2: xg1[row][g] = seq[row][:] . Wih1[g][:] + (bih1+bhh1)[g]
// rows = b*1020+t (522240 = 4080 * 128). M-tile 128 rows, N = 128 gates, K=128.
// ---------------------------------------------------------------------------
__global__ __launch_bounds__(256) void xg_kernel(
    const float* __restrict__ Wih1, const float* __restrict__ bih1, const float* __restrict__ bhh1)
{
    const int row0 = blockIdx.x * 128;
    const int tid  = threadIdx.x;
    const int tx   = tid & 15;     // gate micro
    const int ty   = tid >> 4;     // row micro
    const int g0   = tx * 8;
    const int r0   = ty * 8;

    __shared__ __align__(16) float sa[16][132];  // [c][row]
    __shared__ __align__(16) float sb[16][132];  // [c][gate]
    __shared__ float bs[128];

    if (tid < 128) bs[tid] = bih1[tid] + bhh1[tid];

    u64 acc[4][8];
    #pragma unroll
    for (int m = 0; m < 4; m++)
        #pragma unroll
        for (int n = 0; n < 8; n++) acc[m][n] = 0ULL;

    for (int c0 = 0; c0 < 128; c0 += 16) {
        for (int idx = tid; idx < 2048; idx += 256) {
            int r = idx >> 4, c = idx & 15;
            sa[c][r] = g_conv[(long)(row0 + r) * 128 + c0 + c];
        }
        for (int idx = tid; idx < 2048; idx += 256) {
            int g = idx >> 4, c = idx & 15;
            sb[c][g] = Wih1[g * 128 + c0 + c];
        }
        __syncthreads();
        #pragma unroll
        for (int c = 0; c < 16; c++) {
            const u64* ap = reinterpret_cast<const u64*>(&sa[c][r0]);
            u64 A0 = ap[0], A1 = ap[1], A2 = ap[2], A3 = ap[3];
            const float4* bp = reinterpret_cast<const float4*>(&sb[c][g0]);
            float4 b0 = bp[0], b1 = bp[1];
            u64 pb[8];
            pb[0]=pack2(b0.x,b0.x); pb[1]=pack2(b0.y,b0.y); pb[2]=pack2(b0.z,b0.z); pb[3]=pack2(b0.w,b0.w);
            pb[4]=pack2(b1.x,b1.x); pb[5]=pack2(b1.y,b1.y); pb[6]=pack2(b1.z,b1.z); pb[7]=pack2(b1.w,b1.w);
            #pragma unroll
            for (int n = 0; n < 8; n++) {
                acc[0][n] = fma2(A0, pb[n], acc[0][n]);
                acc[1][n] = fma2(A1, pb[n], acc[1][n]);
                acc[2][n] = fma2(A2, pb[n], acc[2][n]);
                acc[3][n] = fma2(A3, pb[n], acc[3][n]);
            }
        }
        __syncthreads();
    }
    #pragma unroll
    for (int m = 0; m < 4; m++) {
        long re = row0 + r0 + 2 * m;
        #pragma unroll
        for (int n = 0; n < 8; n++) {
            int g = g0 + n;
            g_xg[re * 128 + g]       = lo32(acc[m][n]) + bs[g];
            g_xg[(re + 1) * 128 + g] = hi32(acc[m][n]) + bs[g];
        }
    }
}

// ---------------------------------------------------------------------------
// Kernel 3: fused 3-layer LSTM scan. One block (128 thr) per batch element.
// Thread tid owns gate tid of layer1 (128 gates), gate tid of layer2 (tid<64),
// gate tid of layer3. All recurrent/input weights register-resident.
// PyTorch gate order along rows: [i | f | g | o].
// ---------------------------------------------------------------------------
__device__ __forceinline__ float sigf(float v){ return __fdividef(1.f, 1.f + __expf(-v)); }
__device__ __forceinline__ float tnh(float v){ return 1.f - __fdividef(2.f, __expf(2.f * v) + 1.f); }

__global__ __launch_bounds__(128) void lstm_kernel(
    const float* __restrict__ Whh1,
    const float* __restrict__ Wih2, const float* __restrict__ Whh2,
    const float* __restrict__ bih2, const float* __restrict__ bhh2,
    const float* __restrict__ Wih3, const float* __restrict__ Whh3,
    const float* __restrict__ bih3, const float* __restrict__ bhh3,
    float* __restrict__ out)
{
    const int b   = blockIdx.x;
    const int tid = threadIdx.x;

    __shared__ __align__(16) float s_h1[32];
    __shared__ __align__(16) float s_h2[16];
    __shared__ __align__(16) float s_h3[32];
    __shared__ float s_g1[128], s_g2[64], s_g3[128];

    float w1[32];
    #pragma unroll
    for (int k = 0; k < 32; k++) w1[k] = Whh1[tid * 32 + k];

    float wi2[32], wh2[16], b2 = 0.f;
    if (tid < 64) {
        #pragma unroll
        for (int k = 0; k < 32; k++) wi2[k] = Wih2[tid * 32 + k];
        #pragma unroll
        for (int k = 0; k < 16; k++) wh2[k] = Whh2[tid * 16 + k];
        b2 = bih2[tid] + bhh2[tid];
    }
    float wi3[16], wh3[32];
    #pragma unroll
    for (int k = 0; k < 16; k++) wi3[k] = Wih3[tid * 16 + k];
    #pragma unroll
    for (int k = 0; k < 32; k++) wh3[k] = Whh3[tid * 32 + k];
    float b3 = bih3[tid] + bhh3[tid];

    float c1 = 0.f, c2 = 0.f, c3 = 0.f;
    if (tid < 32) { s_h1[tid] = 0.f; s_h3[tid] = 0.f; }
    if (tid < 16) s_h2[tid] = 0.f;
    __syncthreads();

    const float* xg = g_xg + (long)b * (TSEQ * 128);
    float xv = xg[tid];  // t = 0 pre-gates for this thread's layer1 gate
    for (int t = 0; t < TSEQ; t++) {
        int tn = (t + 1 < TSEQ) ? (t + 1) : t;
        float xnext = xg[tn * 128 + tid];  // prefetch next step

        // ---- layer 1 gates: xg + Whh1 . h1 ----
        {
            float a0 = xv, a1 = 0.f, a2 = 0.f, a3 = 0.f;
            #pragma unroll
            for (int k = 0; k < 32; k += 4) {
                float4 h = *reinterpret_cast<const float4*>(&s_h1[k]);
                a0 += w1[k] * h.x; a1 += w1[k+1] * h.y; a2 += w1[k+2] * h.z; a3 += w1[k+3] * h.w;
            }
            s_g1[tid] = (a0 + a1) + (a2 + a3);
        }
        __syncthreads();
        if (tid < 32) {
            float gi = sigf(s_g1[tid]), gf = sigf(s_g1[32 + tid]);
            float gg = tnh(s_g1[64 + tid]), go = sigf(s_g1[96 + tid]);
            c1 = gf * c1 + gi * gg;
            s_h1[tid] = go * tnh(c1);
        }
        __syncthreads();

        // ---- layer 2 gates: b2 + Wih2 . h1 + Whh2 . h2 ----
        if (tid < 64) {
            float d0 = b2, d1 = 0.f, d2 = 0.f, d3 = 0.f;
            #pragma unroll
            for (int k = 0; k < 32; k += 4) {
                float4 h = *reinterpret_cast<const float4*>(&s_h1[k]);
                d0 += wi2[k] * h.x; d1 += wi2[k+1] * h.y; d2 += wi2[k+2] * h.z; d3 += wi2[k+3] * h.w;
            }
            #pragma unroll
            for (int k = 0; k < 16; k += 4) {
                float4 h = *reinterpret_cast<const float4*>(&s_h2[k]);
                d0 += wh2[k] * h.x; d1 += wh2[k+1] * h.y; d2 += wh2[k+2] * h.z; d3 += wh2[k+3] * h.w;
            }
            s_g2[tid] = (d0 + d1) + (d2 + d3);
        }
        __syncthreads();
        if (tid < 16) {
            float gi = sigf(s_g2[tid]), gf = sigf(s_g2[16 + tid]);
            float gg = tnh(s_g2[32 + tid]), go = sigf(s_g2[48 + tid]);
            c2 = gf * c2 + gi * gg;
            s_h2[tid] = go * tnh(c2);
        }
        __syncthreads();

        // ---- layer 3 gates: b3 + Wih3 . h2 + Whh3 . h3 ----
        {
            float d0 = b3, d1 = 0.f, d2 = 0.f, d3 = 0.f;
            #pragma unroll
            for (int k = 0; k < 16; k += 4) {
                float4 h = *reinterpret_cast<const float4*>(&s_h2[k]);
                d0 += wi3[k] * h.x; d1 += wi3[k+1] * h.y; d2 += wi3[k+2] * h.z; d3 += wi3[k+3] * h.w;
            }
            #pragma unroll
            for (int k = 0; k < 32; k += 4) {
                float4 h = *reinterpret_cast<const float4*>(&s_h3[k]);
                d0 += wh3[k] * h.x; d1 += wh3[k+1] * h.y; d2 += wh3[k+2] * h.z; d3 += wh3[k+3] * h.w;
            }
            s_g3[tid] = (d0 + d1) + (d2 + d3);
        }
        __syncthreads();
        if (tid < 32) {
            float gi = sigf(s_g3[tid]), gf = sigf(s_g3[32 + tid]);
            float gg = tnh(s_g3[64 + tid]), go = sigf(s_g3[96 + tid]);
            c3 = gf * c3 + gi * gg;
            s_h3[tid] = go * tnh(c3);
        }
        __syncthreads();

        xv = xnext;
    }

    if (tid < 32) out[b * 32 + tid] = s_h3[tid];
}

// ---------------------------------------------------------------------------
extern "C" void kernel_launch(void* const* d_in, const int* in_sizes, int n_in,
                              void* d_out, int out_size)
{
    const float* x      = (const float*)d_in[0];
    const float* conv_w = (const float*)d_in[1];
    const float* conv_b = (const float*)d_in[2];
    const float* Wih1   = (const float*)d_in[3];
    const float* Whh1   = (const float*)d_in[4];
    const float* bih1   = (const float*)d_in[5];
    const float* bhh1   = (const float*)d_in[6];
    const float* Wih2   = (const float*)d_in[7];
    const float* Whh2   = (const float*)d_in[8];
    const float* bih2   = (const float*)d_in[9];
    const float* bhh2   = (const float*)d_in[10];
    const float* Wih3   = (const float*)d_in[11];
    const float* Whh3   = (const float*)d_in[12];
    const float* bih3   = (const float*)d_in[13];
    const float* bhh3   = (const float*)d_in[14];
    float* out = (float*)d_out;

    conv_kernel<<<dim3(8, NBATCH), 256>>>(x, conv_w, conv_b);
    xg_kernel<<<(NBATCH * TSEQ) / 128, 256>>>(Wih1, bih1, bhh1);
    lstm_kernel<<<NBATCH, 128>>>(Whh1, Wih2, Whh2, bih2, bhh2,
                                 Wih3, Whh3, bih3, bhh3, out);
}

// round 11
// speedup vs baseline: 1.2507x; 1.2507x over previous
#include <cuda_runtime.h>

typedef unsigned long long u64;

#define NBATCH 512
#define CIN 128
#define LIN 1024
#define LOUT 1020
#define TSEQ 1020

// conv output in [b][ch][pos] layout == seq [b][t][128] flattened (pure re-view)
__device__ float g_conv[NBATCH * CIN * LOUT];
__device__ float g_xg[NBATCH * TSEQ * 128];
__device__ float g_wt[640 * 128];   // transposed conv weight: [ic*5+j][oc]

__device__ __forceinline__ u64 fma2(u64 a, u64 b, u64 c){
    u64 d; asm("fma.rn.f32x2 %0, %1, %2, %3;" : "=l"(d) : "l"(a), "l"(b), "l"(c)); return d;
}
__device__ __forceinline__ u64 pack2(float lo, float hi){
    u64 d; asm("mov.b64 %0, {%1, %2};" : "=l"(d) : "f"(lo), "f"(hi)); return d;
}
__device__ __forceinline__ float lo32(u64 v){ return __uint_as_float((unsigned)(v & 0xffffffffu)); }
__device__ __forceinline__ float hi32(u64 v){ return __uint_as_float((unsigned)(v >> 32)); }

__device__ __forceinline__ void cp16(void* dst_smem, const void* src, int srcbytes){
    unsigned d = (unsigned)__cvta_generic_to_shared(dst_smem);
    asm volatile("cp.async.ca.shared.global [%0], [%1], 16, %2;" :: "r"(d), "l"(src), "r"(srcbytes));
}
__device__ __forceinline__ void cp_commit(){ asm volatile("cp.async.commit_group;"); }

// ---------------------------------------------------------------------------
// Kernel 0: transpose conv weight w[oc][ic][j] -> g_wt[ic*5+j][oc]
// ---------------------------------------------------------------------------
__global__ void prep_kernel(const float* __restrict__ w){
    int i = blockIdx.x * 256 + threadIdx.x;
    if (i < 128 * 640) {
        int oc = i / 640, r = i - oc * 640;
        g_wt[r * 128 + oc] = w[i];
    }
}

// ---------------------------------------------------------------------------
// Kernel 1: conv1d 128->128, k=5, VALID. Implicit GEMM, f32x2 FMAs,
// cp.async double-buffered tiles of 4 input channels.
// ---------------------------------------------------------------------------
#define ICT 4
__global__ __launch_bounds__(256) void conv_kernel(
    const float* __restrict__ x, const float* __restrict__ bias)
{
    __shared__ __align__(16) float xs[2][ICT][132];
    __shared__ __align__(16) float ws[2][ICT * 5][128];

    const int b   = blockIdx.y;
    const int p0  = blockIdx.x * 128;
    const int tid = threadIdx.x;
    const int tx  = tid & 15;
    const int ty  = tid >> 4;
    const int oc0 = ty * 8;
    const int pp0 = tx * 8;

    u64 acc[4][8];
    #pragma unroll
    for (int m = 0; m < 4; m++)
        #pragma unroll
        for (int n = 0; n < 8; n++) acc[m][n] = 0ULL;

    const float* xb = x + (long)b * (CIN * LIN);

    // tile loader: ic0 = it*ICT, into buffer buf
    auto issue_tile = [&](int it, int buf){
        int ic0 = it * ICT;
        // xs: ICT rows x 33 chunks of 16B
        if (tid < ICT * 33) {
            int r = tid / 33, cc = tid - r * 33;
            int gp = p0 + cc * 4;
            int nb = (LIN - gp) * 4;
            nb = nb < 0 ? 0 : (nb > 16 ? 16 : nb);
            int sg = gp > LIN - 4 ? LIN - 4 : gp;
            cp16(&xs[buf][r][cc * 4], xb + (ic0 + r) * LIN + sg, nb);
        }
        // ws: ICT*5 rows x 32 chunks of 16B = 640 copies over 256 threads
        #pragma unroll
        for (int idx = tid; idx < ICT * 5 * 32; idx += 256) {
            int k = idx >> 5, cc = idx & 31;
            cp16(&ws[buf][k][cc * 4], g_wt + (ic0 * 5 + k) * 128 + cc * 4, 16);
        }
        cp_commit();
    };

    issue_tile(0, 0);
    const int NT = CIN / ICT;   // 32
    for (int it = 0; it < NT; it++) {
        int buf = it & 1;
        if (it + 1 < NT) {
            issue_tile(it + 1, buf ^ 1);
            asm volatile("cp.async.wait_group 1;");
        } else {
            asm volatile("cp.async.wait_group 0;");
        }
        __syncthreads();

        #pragma unroll
        for (int icl = 0; icl < ICT; icl++) {
            const float4* wp = reinterpret_cast<const float4*>(&xs[buf][icl][pp0]);
            float4 v0 = wp[0], v1 = wp[1], v2 = wp[2];
            u64 pw[12];
            pw[0]=pack2(v0.x,v0.x); pw[1]=pack2(v0.y,v0.y); pw[2]=pack2(v0.z,v0.z); pw[3]=pack2(v0.w,v0.w);
            pw[4]=pack2(v1.x,v1.x); pw[5]=pack2(v1.y,v1.y); pw[6]=pack2(v1.z,v1.z); pw[7]=pack2(v1.w,v1.w);
            pw[8]=pack2(v2.x,v2.x); pw[9]=pack2(v2.y,v2.y); pw[10]=pack2(v2.z,v2.z); pw[11]=pack2(v2.w,v2.w);
            #pragma unroll
            for (int j = 0; j < 5; j++) {
                const u64* ap = reinterpret_cast<const u64*>(&ws[buf][icl * 5 + j][oc0]);
                u64 a0 = ap[0], a1 = ap[1], a2 = ap[2], a3 = ap[3];
                #pragma unroll
                for (int n = 0; n < 8; n++) {
                    u64 bb = pw[j + n];
                    acc[0][n] = fma2(a0, bb, acc[0][n]);
                    acc[1][n] = fma2(a1, bb, acc[1][n]);
                    acc[2][n] = fma2(a2, bb, acc[2][n]);
                    acc[3][n] = fma2(a3, bb, acc[3][n]);
                }
            }
        }
        __syncthreads();
    }

    float* ob = g_conv + (long)b * (CIN * LOUT);
    #pragma unroll
    for (int m = 0; m < 4; m++) {
        int oce = oc0 + 2 * m;
        float be = bias[oce], bo = bias[oce + 1];
        #pragma unroll
        for (int n = 0; n < 8; n++) {
            int p = p0 + pp0 + n;
            if (p < LOUT) {
                ob[oce * LOUT + p]       = lo32(acc[m][n]) + be;
                ob[(oce + 1) * LOUT + p] = hi32(acc[m][n]) + bo;
            }
        }
    }
}

// ---------------------------------------------------------------------------
// Kernel 2: xg1[row][g] = seq[row][:] . Wih1[g][:] + (bih1+bhh1)[g]
// Register-staged prefetch double buffering (single smem buffer, 2 syncs).
// ---------------------------------------------------------------------------
__global__ __launch_bounds__(256) void xg_kernel(
    const float* __restrict__ Wih1, const float* __restrict__ bih1, const float* __restrict__ bhh1)
{
    const int row0 = blockIdx.x * 128;
    const int tid  = threadIdx.x;
    const int tx   = tid & 15;
    const int ty   = tid >> 4;
    const int g0   = tx * 8;
    const int r0   = ty * 8;

    __shared__ __align__(16) float sa[16][132];
    __shared__ __align__(16) float sb[16][132];
    __shared__ float bs[128];

    if (tid < 128) bs[tid] = bih1[tid] + bhh1[tid];

    u64 acc[4][8];
    #pragma unroll
    for (int m = 0; m < 4; m++)
        #pragma unroll
        for (int n = 0; n < 8; n++) acc[m][n] = 0ULL;

    const int lr = tid >> 4;      // row/gate index for loads
    const int lc = tid & 15;      // channel index for loads

    float ra[8], rb[8];
    #pragma unroll
    for (int i = 0; i < 8; i++) {
        int rr = lr + i * 16;
        ra[i] = g_conv[(long)(row0 + rr) * 128 + lc];
        rb[i] = Wih1[rr * 128 + lc];
    }

    for (int t = 0; t < 8; t++) {
        #pragma unroll
        for (int i = 0; i < 8; i++) {
            int rr = lr + i * 16;
            sa[lc][rr] = ra[i];
            sb[lc][rr] = rb[i];
        }
        __syncthreads();
        if (t + 1 < 8) {
            int c0 = (t + 1) * 16;
            #pragma unroll
            for (int i = 0; i < 8; i++) {
                int rr = lr + i * 16;
                ra[i] = g_conv[(long)(row0 + rr) * 128 + c0 + lc];
                rb[i] = Wih1[rr * 128 + c0 + lc];
            }
        }
        #pragma unroll
        for (int c = 0; c < 16; c++) {
            const u64* ap = reinterpret_cast<const u64*>(&sa[c][r0]);
            u64 A0 = ap[0], A1 = ap[1], A2 = ap[2], A3 = ap[3];
            const float4* bp = reinterpret_cast<const float4*>(&sb[c][g0]);
            float4 b0 = bp[0], b1 = bp[1];
            u64 pb[8];
            pb[0]=pack2(b0.x,b0.x); pb[1]=pack2(b0.y,b0.y); pb[2]=pack2(b0.z,b0.z); pb[3]=pack2(b0.w,b0.w);
            pb[4]=pack2(b1.x,b1.x); pb[5]=pack2(b1.y,b1.y); pb[6]=pack2(b1.z,b1.z); pb[7]=pack2(b1.w,b1.w);
            #pragma unroll
            for (int n = 0; n < 8; n++) {
                acc[0][n] = fma2(A0, pb[n], acc[0][n]);
                acc[1][n] = fma2(A1, pb[n], acc[1][n]);
                acc[2][n] = fma2(A2, pb[n], acc[2][n]);
                acc[3][n] = fma2(A3, pb[n], acc[3][n]);
            }
        }
        __syncthreads();
    }
    #pragma unroll
    for (int m = 0; m < 4; m++) {
        long re = row0 + r0 + 2 * m;
        #pragma unroll
        for (int n = 0; n < 8; n++) {
            int g = g0 + n;
            g_xg[re * 128 + g]       = lo32(acc[m][n]) + bs[g];
            g_xg[(re + 1) * 128 + g] = hi32(acc[m][n]) + bs[g];
        }
    }
}

// ---------------------------------------------------------------------------
// Kernel 3: fused 3-layer LSTM scan with cross-layer software pipelining.
// Iteration n computes g1(n), g2(n-1), g3(n-2) in one phase (2 syncs/step).
// Phase-B updater threads: layer1 = tid 0..31, layer2 = tid 64..79 (they own
// c2), layer3 = tid 96..127. All other threads idle in phase B.
// ---------------------------------------------------------------------------
__device__ __forceinline__ float sigf(float v){ return __fdividef(1.f, 1.f + __expf(-v)); }
__device__ __forceinline__ float tnh(float v){ return 1.f - __fdividef(2.f, __expf(2.f * v) + 1.f); }

__global__ __launch_bounds__(128, 3) void lstm_kernel(
    const float* __restrict__ Whh1,
    const float* __restrict__ Wih2, const float* __restrict__ Whh2,
    const float* __restrict__ bih2, const float* __restrict__ bhh2,
    const float* __restrict__ Wih3, const float* __restrict__ Whh3,
    const float* __restrict__ bih3, const float* __restrict__ bhh3,
    float* __restrict__ out)
{
    const int b   = blockIdx.x;
    const int tid = threadIdx.x;

    __shared__ __align__(16) float s_h1[32];
    __shared__ __align__(16) float s_h2[16];
    __shared__ __align__(16) float s_h3[32];
    __shared__ float s_g1[128], s_g2a[64], s_g2b[64], s_g3[128];

    // weight pairs (u64 = two adjacent fp32)
    u64 w1p[16];
    {
        const u64* W = reinterpret_cast<const u64*>(Whh1 + tid * 32);
        #pragma unroll
        for (int k = 0; k < 16; k++) w1p[k] = W[k];
    }
    u64 wi2p[16]; u64 wh2p[8]; float b2 = 0.f;
    if (tid < 64) {
        const u64* W = reinterpret_cast<const u64*>(Wih2 + tid * 32);
        #pragma unroll
        for (int k = 0; k < 16; k++) wi2p[k] = W[k];
        b2 = bih2[tid] + bhh2[tid];
    } else {
        const u64* W = reinterpret_cast<const u64*>(Whh2 + (tid - 64) * 16);
        #pragma unroll
        for (int k = 0; k < 8; k++) wh2p[k] = W[k];
    }
    u64 wi3p[8], wh3p[16];
    {
        const u64* Wa = reinterpret_cast<const u64*>(Wih3 + tid * 16);
        #pragma unroll
        for (int k = 0; k < 8; k++) wi3p[k] = Wa[k];
        const u64* Wb = reinterpret_cast<const u64*>(Whh3 + tid * 32);
        #pragma unroll
        for (int k = 0; k < 16; k++) wh3p[k] = Wb[k];
    }
    float b3 = bih3[tid] + bhh3[tid];

    float c1 = 0.f, c2 = 0.f, c3 = 0.f;
    if (tid < 32) { s_h1[tid] = 0.f; s_h3[tid] = 0.f; }
    if (tid < 16) s_h2[tid] = 0.f;
    __syncthreads();

    const float* xg = g_xg + (long)b * (TSEQ * 128);
    float xa = xg[tid];             // pre-gate for n = 0
    float xb2 = xg[128 + tid];      // n = 1

    for (int n = 0; n < TSEQ + 2; n++) {
        int np = (n + 2 < TSEQ) ? n + 2 : TSEQ - 1;
        float xc = xg[np * 128 + tid];

        const u64* h1p = reinterpret_cast<const u64*>(s_h1);
        const u64* h2p = reinterpret_cast<const u64*>(s_h2);
        const u64* h3p = reinterpret_cast<const u64*>(s_h3);

        // ---- g1 for time n ----
        u64 A0 = 0ULL, A1 = 0ULL;
        #pragma unroll
        for (int k = 0; k < 16; k += 2) {
            A0 = fma2(w1p[k],     h1p[k],     A0);
            A1 = fma2(w1p[k + 1], h1p[k + 1], A1);
        }
        float g1v = xa + (lo32(A0) + hi32(A0)) + (lo32(A1) + hi32(A1));

        // ---- g2 halves for time n-1 ----
        float g2v;
        if (tid < 64) {
            u64 B0 = 0ULL, B1 = 0ULL;
            #pragma unroll
            for (int k = 0; k < 16; k += 2) {
                B0 = fma2(wi2p[k],     h1p[k],     B0);
                B1 = fma2(wi2p[k + 1], h1p[k + 1], B1);
            }
            g2v = b2 + (lo32(B0) + hi32(B0)) + (lo32(B1) + hi32(B1));
        } else {
            u64 B0 = 0ULL;
            #pragma unroll
            for (int k = 0; k < 8; k++) B0 = fma2(wh2p[k], h2p[k], B0);
            g2v = lo32(B0) + hi32(B0);
        }

        // ---- g3 for time n-2 ----
        u64 C0 = 0ULL, C1 = 0ULL;
        #pragma unroll
        for (int k = 0; k < 8; k++) C0 = fma2(wi3p[k], h2p[k], C0);
        #pragma unroll
        for (int k = 0; k < 16; k += 2) {
            C0 = fma2(wh3p[k],     h3p[k],     C0);
            C1 = fma2(wh3p[k + 1], h3p[k + 1], C1);
        }
        float g3v = b3 + (lo32(C0) + hi32(C0)) + (lo32(C1) + hi32(C1));

        s_g1[tid] = g1v;
        if (tid < 64) s_g2a[tid] = g2v; else s_g2b[tid - 64] = g2v;
        s_g3[tid] = g3v;
        __syncthreads();

        if (tid < 32) {
            // layer 1 cell update (valid n < TSEQ)
            if (n < TSEQ) {
                float gi = sigf(s_g1[tid]),      gf = sigf(s_g1[32 + tid]);
                float gg = tnh(s_g1[64 + tid]),  go = sigf(s_g1[96 + tid]);
                c1 = gf * c1 + gi * gg;
                s_h1[tid] = go * tnh(c1);
            }
        } else if (tid >= 64 && tid < 80) {
            // layer 2 cell update for time n-1 (these threads own c2)
            int j = tid - 64;
            if (n >= 1 && n <= TSEQ) {
                float vi = s_g2a[j]      + s_g2b[j];
                float vf = s_g2a[16 + j] + s_g2b[16 + j];
                float vg = s_g2a[32 + j] + s_g2b[32 + j];
                float vo = s_g2a[48 + j] + s_g2b[48 + j];
                c2 = sigf(vf) * c2 + sigf(vi) * tnh(vg);
                s_h2[j] = sigf(vo) * tnh(c2);
            }
        } else if (tid >= 96) {
            // layer 3 cell update for time n-2
            int j = tid - 96;
            if (n >= 2) {
                float gi = sigf(s_g3[j]),      gf = sigf(s_g3[32 + j]);
                float gg = tnh(s_g3[64 + j]),  go = sigf(s_g3[96 + j]);
                c3 = gf * c3 + gi * gg;
                s_h3[j] = go * tnh(c3);
            }
        }
        __syncthreads();

        xa = xb2; xb2 = xc;
    }

    if (tid < 32) out[b * 32 + tid] = s_h3[tid];
}

// ---------------------------------------------------------------------------
extern "C" void kernel_launch(void* const* d_in, const int* in_sizes, int n_in,
                              void* d_out, int out_size)
{
    const float* x      = (const float*)d_in[0];
    const float* conv_w = (const float*)d_in[1];
    const float* conv_b = (const float*)d_in[2];
    const float* Wih1   = (const float*)d_in[3];
    const float* Whh1   = (const float*)d_in[4];
    const float* bih1   = (const float*)d_in[5];
    const float* bhh1   = (const float*)d_in[6];
    const float* Wih2   = (const float*)d_in[7];
    const float* Whh2   = (const float*)d_in[8];
    const float* bih2   = (const float*)d_in[9];
    const float* bhh2   = (const float*)d_in[10];
    const float* Wih3   = (const float*)d_in[11];
    const float* Whh3   = (const float*)d_in[12];
    const float* bih3   = (const float*)d_in[13];
    const float* bhh3   = (const float*)d_in[14];
    float* out = (float*)d_out;

    prep_kernel<<<(128 * 640 + 255) / 256, 256>>>(conv_w);
    conv_kernel<<<dim3(8, NBATCH), 256>>>(x, conv_b);
    xg_kernel<<<(NBATCH * TSEQ) / 128, 256>>>(Wih1, bih1, bhh1);
    lstm_kernel<<<NBATCH, 128>>>(Whh1, Wih2, Whh2, bih2, bhh2,
                                 Wih3, Whh3, bih3, bhh3, out);
}

// round 12
// speedup vs baseline: 1.2663x; 1.0125x over previous
#include <cuda_runtime.h>

typedef unsigned long long u64;

#define NBATCH 512
#define CIN 128
#define LIN 1024
#define LOUT 1020
#define TSEQ 1020

// conv output in [b][ch][pos] layout == seq [b][t][128] flattened (pure re-view)
__device__ float g_conv[NBATCH * CIN * LOUT];
__device__ float g_xg[NBATCH * TSEQ * 128];
__device__ float g_wt[640 * 128];   // transposed conv weight: [ic*5+j][oc]

__device__ __forceinline__ u64 fma2(u64 a, u64 b, u64 c){
    u64 d; asm("fma.rn.f32x2 %0, %1, %2, %3;" : "=l"(d) : "l"(a), "l"(b), "l"(c)); return d;
}
__device__ __forceinline__ u64 pack2(float lo, float hi){
    u64 d; asm("mov.b64 %0, {%1, %2};" : "=l"(d) : "f"(lo), "f"(hi)); return d;
}
__device__ __forceinline__ float lo32(u64 v){ return __uint_as_float((unsigned)(v & 0xffffffffu)); }
__device__ __forceinline__ float hi32(u64 v){ return __uint_as_float((unsigned)(v >> 32)); }

__device__ __forceinline__ void cp16(void* dst_smem, const void* src, int srcbytes){
    unsigned d = (unsigned)__cvta_generic_to_shared(dst_smem);
    asm volatile("cp.async.ca.shared.global [%0], [%1], 16, %2;" :: "r"(d), "l"(src), "r"(srcbytes));
}
__device__ __forceinline__ void cp_commit(){ asm volatile("cp.async.commit_group;"); }

// ---------------------------------------------------------------------------
// Kernel 0: transpose conv weight w[oc][ic][j] -> g_wt[ic*5+j][oc]
// ---------------------------------------------------------------------------
__global__ void prep_kernel(const float* __restrict__ w){
    int i = blockIdx.x * 256 + threadIdx.x;
    if (i < 128 * 640) {
        int oc = i / 640, r = i - oc * 640;
        g_wt[r * 128 + oc] = w[i];
    }
}

// ---------------------------------------------------------------------------
// Kernel 1: conv1d 128->128, k=5, VALID. Implicit GEMM, f32x2 FMAs,
// cp.async double-buffered tiles of 8 input channels (16 barrier pairs).
// ---------------------------------------------------------------------------
#define ICT 8
__global__ __launch_bounds__(256) void conv_kernel(
    const float* __restrict__ x, const float* __restrict__ bias)
{
    __shared__ __align__(16) float xs[2][ICT][132];
    __shared__ __align__(16) float ws[2][ICT * 5][128];

    const int b   = blockIdx.y;
    const int p0  = blockIdx.x * 128;
    const int tid = threadIdx.x;
    const int tx  = tid & 15;
    const int ty  = tid >> 4;
    const int oc0 = ty * 8;
    const int pp0 = tx * 8;

    u64 acc[4][8];
    #pragma unroll
    for (int m = 0; m < 4; m++)
        #pragma unroll
        for (int n = 0; n < 8; n++) acc[m][n] = 0ULL;

    const float* xb = x + (long)b * (CIN * LIN);

    // tile loader: ic0 = it*ICT, into buffer buf
    auto issue_tile = [&](int it, int buf){
        int ic0 = it * ICT;
        // xs: ICT rows x 33 chunks of 16B = 264 copies
        for (int idx = tid; idx < ICT * 33; idx += 256) {
            int r = idx / 33, cc = idx - r * 33;
            int gp = p0 + cc * 4;
            int nb = (LIN - gp) * 4;
            nb = nb < 0 ? 0 : (nb > 16 ? 16 : nb);
            int sg = gp > LIN - 4 ? LIN - 4 : gp;
            cp16(&xs[buf][r][cc * 4], xb + (ic0 + r) * LIN + sg, nb);
        }
        // ws: ICT*5 rows x 32 chunks of 16B = 1280 copies
        #pragma unroll
        for (int idx = tid; idx < ICT * 5 * 32; idx += 256) {
            int k = idx >> 5, cc = idx & 31;
            cp16(&ws[buf][k][cc * 4], g_wt + (ic0 * 5 + k) * 128 + cc * 4, 16);
        }
        cp_commit();
    };

    issue_tile(0, 0);
    const int NT = CIN / ICT;   // 16
    for (int it = 0; it < NT; it++) {
        int buf = it & 1;
        if (it + 1 < NT) {
            issue_tile(it + 1, buf ^ 1);
            asm volatile("cp.async.wait_group 1;");
        } else {
            asm volatile("cp.async.wait_group 0;");
        }
        __syncthreads();

        #pragma unroll
        for (int icl = 0; icl < ICT; icl++) {
            const float4* wp = reinterpret_cast<const float4*>(&xs[buf][icl][pp0]);
            float4 v0 = wp[0], v1 = wp[1], v2 = wp[2];
            u64 pw[12];
            pw[0]=pack2(v0.x,v0.x); pw[1]=pack2(v0.y,v0.y); pw[2]=pack2(v0.z,v0.z); pw[3]=pack2(v0.w,v0.w);
            pw[4]=pack2(v1.x,v1.x); pw[5]=pack2(v1.y,v1.y); pw[6]=pack2(v1.z,v1.z); pw[7]=pack2(v1.w,v1.w);
            pw[8]=pack2(v2.x,v2.x); pw[9]=pack2(v2.y,v2.y); pw[10]=pack2(v2.z,v2.z); pw[11]=pack2(v2.w,v2.w);
            #pragma unroll
            for (int j = 0; j < 5; j++) {
                const u64* ap = reinterpret_cast<const u64*>(&ws[buf][icl * 5 + j][oc0]);
                u64 a0 = ap[0], a1 = ap[1], a2 = ap[2], a3 = ap[3];
                #pragma unroll
                for (int n = 0; n < 8; n++) {
                    u64 bb = pw[j + n];
                    acc[0][n] = fma2(a0, bb, acc[0][n]);
                    acc[1][n] = fma2(a1, bb, acc[1][n]);
                    acc[2][n] = fma2(a2, bb, acc[2][n]);
                    acc[3][n] = fma2(a3, bb, acc[3][n]);
                }
            }
        }
        __syncthreads();
    }

    float* ob = g_conv + (long)b * (CIN * LOUT);
    #pragma unroll
    for (int m = 0; m < 4; m++) {
        int oce = oc0 + 2 * m;
        float be = bias[oce], bo = bias[oce + 1];
        #pragma unroll
        for (int n = 0; n < 8; n++) {
            int p = p0 + pp0 + n;
            if (p < LOUT) {
                ob[oce * LOUT + p]       = lo32(acc[m][n]) + be;
                ob[(oce + 1) * LOUT + p] = hi32(acc[m][n]) + bo;
            }
        }
    }
}

// ---------------------------------------------------------------------------
// Kernel 2: xg1[row][g] = seq[row][:] . Wih1[g][:] + (bih1+bhh1)[g]
// Register-staged prefetch double buffering (single smem buffer, 2 syncs).
// ---------------------------------------------------------------------------
__global__ __launch_bounds__(256) void xg_kernel(
    const float* __restrict__ Wih1, const float* __restrict__ bih1, const float* __restrict__ bhh1)
{
    const int row0 = blockIdx.x * 128;
    const int tid  = threadIdx.x;
    const int tx   = tid & 15;
    const int ty   = tid >> 4;
    const int g0   = tx * 8;
    const int r0   = ty * 8;

    __shared__ __align__(16) float sa[16][132];
    __shared__ __align__(16) float sb[16][132];
    __shared__ float bs[128];

    if (tid < 128) bs[tid] = bih1[tid] + bhh1[tid];

    u64 acc[4][8];
    #pragma unroll
    for (int m = 0; m < 4; m++)
        #pragma unroll
        for (int n = 0; n < 8; n++) acc[m][n] = 0ULL;

    const int lr = tid >> 4;      // row/gate index for loads
    const int lc = tid & 15;      // channel index for loads

    float ra[8], rb[8];
    #pragma unroll
    for (int i = 0; i < 8; i++) {
        int rr = lr + i * 16;
        ra[i] = g_conv[(long)(row0 + rr) * 128 + lc];
        rb[i] = Wih1[rr * 128 + lc];
    }

    for (int t = 0; t < 8; t++) {
        #pragma unroll
        for (int i = 0; i < 8; i++) {
            int rr = lr + i * 16;
            sa[lc][rr] = ra[i];
            sb[lc][rr] = rb[i];
        }
        __syncthreads();
        if (t + 1 < 8) {
            int c0 = (t + 1) * 16;
            #pragma unroll
            for (int i = 0; i < 8; i++) {
                int rr = lr + i * 16;
                ra[i] = g_conv[(long)(row0 + rr) * 128 + c0 + lc];
                rb[i] = Wih1[rr * 128 + c0 + lc];
            }
        }
        #pragma unroll
        for (int c = 0; c < 16; c++) {
            const u64* ap = reinterpret_cast<const u64*>(&sa[c][r0]);
            u64 A0 = ap[0], A1 = ap[1], A2 = ap[2], A3 = ap[3];
            const float4* bp = reinterpret_cast<const float4*>(&sb[c][g0]);
            float4 b0 = bp[0], b1 = bp[1];
            u64 pb[8];
            pb[0]=pack2(b0.x,b0.x); pb[1]=pack2(b0.y,b0.y); pb[2]=pack2(b0.z,b0.z); pb[3]=pack2(b0.w,b0.w);
            pb[4]=pack2(b1.x,b1.x); pb[5]=pack2(b1.y,b1.y); pb[6]=pack2(b1.z,b1.z); pb[7]=pack2(b1.w,b1.w);
            #pragma unroll
            for (int n = 0; n < 8; n++) {
                acc[0][n] = fma2(A0, pb[n], acc[0][n]);
                acc[1][n] = fma2(A1, pb[n], acc[1][n]);
                acc[2][n] = fma2(A2, pb[n], acc[2][n]);
                acc[3][n] = fma2(A3, pb[n], acc[3][n]);
            }
        }
        __syncthreads();
    }
    #pragma unroll
    for (int m = 0; m < 4; m++) {
        long re = row0 + r0 + 2 * m;
        #pragma unroll
        for (int n = 0; n < 8; n++) {
            int g = g0 + n;
            g_xg[re * 128 + g]       = lo32(acc[m][n]) + bs[g];
            g_xg[(re + 1) * 128 + g] = hi32(acc[m][n]) + bs[g];
        }
    }
}

// ---------------------------------------------------------------------------
// Kernel 3: fused 3-layer LSTM scan with cross-layer software pipelining.
// Iteration n computes g1(n), g2(n-1), g3(n-2) in one phase (2 syncs/step).
// Register diet for 4 blocks/SM (one wave of 512):
//   - wi2/wh2 share one 16-u64 array (branches are disjoint)
//   - Wih3 lives in shared memory, [k][tid] layout (conflict-free LDS.64)
// ---------------------------------------------------------------------------
__device__ __forceinline__ float sigf(float v){ return __fdividef(1.f, 1.f + __expf(-v)); }
__device__ __forceinline__ float tnh(float v){ return 1.f - __fdividef(2.f, __expf(2.f * v) + 1.f); }

__global__ __launch_bounds__(128, 4) void lstm_kernel(
    const float* __restrict__ Whh1,
    const float* __restrict__ Wih2, const float* __restrict__ Whh2,
    const float* __restrict__ bih2, const float* __restrict__ bhh2,
    const float* __restrict__ Wih3, const float* __restrict__ Whh3,
    const float* __restrict__ bih3, const float* __restrict__ bhh3,
    float* __restrict__ out)
{
    const int b   = blockIdx.x;
    const int tid = threadIdx.x;

    __shared__ __align__(16) float s_h1[32];
    __shared__ __align__(16) float s_h2[16];
    __shared__ __align__(16) float s_h3[32];
    __shared__ float s_g1[128], s_g2a[64], s_g2b[64], s_g3[128];
    __shared__ __align__(16) u64 s_wi3[8][128];   // Wih3 pairs: [k][gate]

    // weight pairs (u64 = two adjacent fp32)
    u64 w1p[16];
    {
        const u64* W = reinterpret_cast<const u64*>(Whh1 + tid * 32);
        #pragma unroll
        for (int k = 0; k < 16; k++) w1p[k] = W[k];
    }
    // merged layer-2 weights: tid<64 -> Wih2 row (16 u64); tid>=64 -> Whh2 row (8 u64)
    u64 w2[16]; float b2 = 0.f;
    if (tid < 64) {
        const u64* W = reinterpret_cast<const u64*>(Wih2 + tid * 32);
        #pragma unroll
        for (int k = 0; k < 16; k++) w2[k] = W[k];
        b2 = bih2[tid] + bhh2[tid];
    } else {
        const u64* W = reinterpret_cast<const u64*>(Whh2 + (tid - 64) * 16);
        #pragma unroll
        for (int k = 0; k < 8; k++) w2[k] = W[k];
        #pragma unroll
        for (int k = 8; k < 16; k++) w2[k] = 0ULL;
    }
    // Wih3 row -> shared, transposed layout
    {
        const u64* Wa = reinterpret_cast<const u64*>(Wih3 + tid * 16);
        #pragma unroll
        for (int k = 0; k < 8; k++) s_wi3[k][tid] = Wa[k];
    }
    u64 wh3p[16];
    {
        const u64* Wb = reinterpret_cast<const u64*>(Whh3 + tid * 32);
        #pragma unroll
        for (int k = 0; k < 16; k++) wh3p[k] = Wb[k];
    }
    float b3 = bih3[tid] + bhh3[tid];

    float c1 = 0.f, c2 = 0.f, c3 = 0.f;
    if (tid < 32) { s_h1[tid] = 0.f; s_h3[tid] = 0.f; }
    if (tid < 16) s_h2[tid] = 0.f;
    __syncthreads();

    const float* xg = g_xg + (long)b * (TSEQ * 128);
    float xa = xg[tid];             // pre-gate for n = 0
    float xb2 = xg[128 + tid];      // n = 1

    for (int n = 0; n < TSEQ + 2; n++) {
        int np = (n + 2 < TSEQ) ? n + 2 : TSEQ - 1;
        float xc = xg[np * 128 + tid];

        const u64* h1p = reinterpret_cast<const u64*>(s_h1);
        const u64* h2p = reinterpret_cast<const u64*>(s_h2);
        const u64* h3p = reinterpret_cast<const u64*>(s_h3);

        // ---- g1 for time n ----
        u64 A0 = 0ULL, A1 = 0ULL;
        #pragma unroll
        for (int k = 0; k < 16; k += 2) {
            A0 = fma2(w1p[k],     h1p[k],     A0);
            A1 = fma2(w1p[k + 1], h1p[k + 1], A1);
        }
        float g1v = xa + (lo32(A0) + hi32(A0)) + (lo32(A1) + hi32(A1));

        // ---- g2 halves for time n-1 ----
        float g2v;
        if (tid < 64) {
            u64 B0 = 0ULL, B1 = 0ULL;
            #pragma unroll
            for (int k = 0; k < 16; k += 2) {
                B0 = fma2(w2[k],     h1p[k],     B0);
                B1 = fma2(w2[k + 1], h1p[k + 1], B1);
            }
            g2v = b2 + (lo32(B0) + hi32(B0)) + (lo32(B1) + hi32(B1));
        } else {
            u64 B0 = 0ULL;
            #pragma unroll
            for (int k = 0; k < 8; k++) B0 = fma2(w2[k], h2p[k], B0);
            g2v = lo32(B0) + hi32(B0);
        }

        // ---- g3 for time n-2 ----
        u64 C0 = 0ULL, C1 = 0ULL;
        #pragma unroll
        for (int k = 0; k < 8; k++) C0 = fma2(s_wi3[k][tid], h2p[k], C0);
        #pragma unroll
        for (int k = 0; k < 16; k += 2) {
            C0 = fma2(wh3p[k],     h3p[k],     C0);
            C1 = fma2(wh3p[k + 1], h3p[k + 1], C1);
        }
        float g3v = b3 + (lo32(C0) + hi32(C0)) + (lo32(C1) + hi32(C1));

        s_g1[tid] = g1v;
        if (tid < 64) s_g2a[tid] = g2v; else s_g2b[tid - 64] = g2v;
        s_g3[tid] = g3v;
        __syncthreads();

        if (tid < 32) {
            // layer 1 cell update (valid n < TSEQ)
            if (n < TSEQ) {
                float gi = sigf(s_g1[tid]),      gf = sigf(s_g1[32 + tid]);
                float gg = tnh(s_g1[64 + tid]),  go = sigf(s_g1[96 + tid]);
                c1 = gf * c1 + gi * gg;
                s_h1[tid] = go * tnh(c1);
            }
        } else if (tid >= 64 && tid < 80) {
            // layer 2 cell update for time n-1 (these threads own c2)
            int j = tid - 64;
            if (n >= 1 && n <= TSEQ) {
                float vi = s_g2a[j]      + s_g2b[j];
                float vf = s_g2a[16 + j] + s_g2b[16 + j];
                float vg = s_g2a[32 + j] + s_g2b[32 + j];
                float vo = s_g2a[48 + j] + s_g2b[48 + j];
                c2 = sigf(vf) * c2 + sigf(vi) * tnh(vg);
                s_h2[j] = sigf(vo) * tnh(c2);
            }
        } else if (tid >= 96) {
            // layer 3 cell update for time n-2
            int j = tid - 96;
            if (n >= 2) {
                float gi = sigf(s_g3[j]),      gf = sigf(s_g3[32 + j]);
                float gg = tnh(s_g3[64 + j]),  go = sigf(s_g3[96 + j]);
                c3 = gf * c3 + gi * gg;
                s_h3[j] = go * tnh(c3);
            }
        }
        __syncthreads();

        xa = xb2; xb2 = xc;
    }

    if (tid < 32) out[b * 32 + tid] = s_h3[tid];
}

// ---------------------------------------------------------------------------
extern "C" void kernel_launch(void* const* d_in, const int* in_sizes, int n_in,
                              void* d_out, int out_size)
{
    const float* x      = (const float*)d_in[0];
    const float* conv_w = (const float*)d_in[1];
    const float* conv_b = (const float*)d_in[2];
    const float* Wih1   = (const float*)d_in[3];
    const float* Whh1   = (const float*)d_in[4];
    const float* bih1   = (const float*)d_in[5];
    const float* bhh1   = (const float*)d_in[6];
    const float* Wih2   = (const float*)d_in[7];
    const float* Whh2   = (const float*)d_in[8];
    const float* bih2   = (const float*)d_in[9];
    const float* bhh2   = (const float*)d_in[10];
    const float* Wih3   = (const float*)d_in[11];
    const float* Whh3   = (const float*)d_in[12];
    const float* bih3   = (const float*)d_in[13];
    const float* bhh3   = (const float*)d_in[14];
    float* out = (float*)d_out;

    prep_kernel<<<(128 * 640 + 255) / 256, 256>>>(conv_w);
    conv_kernel<<<dim3(8, NBATCH), 256>>>(x, conv_b);
    xg_kernel<<<(NBATCH * TSEQ) / 128, 256>>>(Wih1, bih1, bhh1);
    lstm_kernel<<<NBATCH, 128>>>(Whh1, Wih2, Whh2, bih2, bhh2,
                                 Wih3, Whh3, bih3, bhh3, out);
}